// round 1
// baseline (speedup 1.0000x reference)
#include <cuda_runtime.h>
#include <cstdint>

// Bipartite COO SpMM:
//   user_agg[u] += val * item_emb[c]  for each edge (u, c, val)
//   item_agg[c] += val * user_emb[u]
// d_out = [user_agg (200000x128) | item_agg (100000x128)], fp32.

#define DIM 128

__device__ __forceinline__ void red_add_v4(float* addr, float4 v) {
    asm volatile("red.global.add.v4.f32 [%0], {%1, %2, %3, %4};"
                 :: "l"(addr), "f"(v.x), "f"(v.y), "f"(v.z), "f"(v.w)
                 : "memory");
}

__global__ void __launch_bounds__(256)
spmm_coo_kernel(const float* __restrict__ user_emb,
                const float* __restrict__ item_emb,
                const float* __restrict__ mat_val,
                const int*   __restrict__ mat_row,
                const int*   __restrict__ mat_col,
                float* __restrict__ user_out,
                float* __restrict__ item_out,
                int nnz)
{
    const int warp_id = (blockIdx.x * blockDim.x + threadIdx.x) >> 5;
    const int lane = threadIdx.x & 31;
    if (warp_id >= nnz) return;

    const int   r = mat_row[warp_id];
    const int   c = mat_col[warp_id];
    const float v = mat_val[warp_id];

    const size_t uoff = (size_t)r * DIM + lane * 4;
    const size_t ioff = (size_t)c * DIM + lane * 4;

    const float4 iv = *reinterpret_cast<const float4*>(item_emb + ioff);
    const float4 uv = *reinterpret_cast<const float4*>(user_emb + uoff);

    float4 umsg = make_float4(v * iv.x, v * iv.y, v * iv.z, v * iv.w);
    float4 imsg = make_float4(v * uv.x, v * uv.y, v * uv.z, v * uv.w);

    red_add_v4(user_out + uoff, umsg);
    red_add_v4(item_out + ioff, imsg);
}

extern "C" void kernel_launch(void* const* d_in, const int* in_sizes, int n_in,
                              void* d_out, int out_size)
{
    const float* user_emb = (const float*)d_in[0];  // 200000*128
    const float* item_emb = (const float*)d_in[1];  // 100000*128
    const float* mat_val  = (const float*)d_in[2];  // 3000000
    const int*   mat_row  = (const int*)d_in[3];    // 3000000
    const int*   mat_col  = (const int*)d_in[4];    // 3000000

    const int nnz     = in_sizes[2];
    const int n_users = in_sizes[0] / DIM;

    float* user_out = (float*)d_out;
    float* item_out = (float*)d_out + (size_t)n_users * DIM;

    // zero accumulators (capturable memset node)
    cudaMemsetAsync(d_out, 0, (size_t)out_size * sizeof(float), 0);

    // one warp per edge, 8 warps per block
    const int threads = 256;
    const int warps_per_block = threads / 32;
    const int blocks = (nnz + warps_per_block - 1) / warps_per_block;
    spmm_coo_kernel<<<blocks, threads>>>(user_emb, item_emb, mat_val,
                                         mat_row, mat_col,
                                         user_out, item_out, nnz);
}

// round 2
// speedup vs baseline: 1.2862x; 1.2862x over previous
#include <cuda_runtime.h>
#include <cstdint>

// Bipartite COO SpMM, processed in 8 L2-resident passes:
//   {user side, item side} x {4 column slices of 32 floats each}.
// Per pass: hot set = gather-table slice + accumulator slice (<= 38.4 MB),
// so gathers and atomics resolve in L2 instead of HBM.
//
// d_out = [user_agg (200000x128) | item_agg (100000x128)], fp32.

#define DIM 128
#define SLICE_W 32                // floats per slice
#define THREADS_PER_EDGE 8        // SLICE_W / 4 (float4 per thread)

__device__ __forceinline__ void red_add_v4(float* addr, float4 v) {
    asm volatile("red.global.add.v4.f32 [%0], {%1, %2, %3, %4};"
                 :: "l"(addr), "f"(v.x), "f"(v.y), "f"(v.z), "f"(v.w)
                 : "memory");
}

// One pass: for each edge e, out[sidx[e], slice] += val[e] * table[gidx[e], slice]
__global__ void __launch_bounds__(256)
spmm_slice_kernel(const float* __restrict__ table,   // gather source
                  float*       __restrict__ out,     // scatter destination
                  const int*   __restrict__ gidx,    // gather row index per edge
                  const int*   __restrict__ sidx,    // scatter row index per edge
                  const float* __restrict__ val,
                  int nnz, int slice_off)
{
    const int t = blockIdx.x * blockDim.x + threadIdx.x;
    const int e = t >> 3;                 // THREADS_PER_EDGE = 8
    if (e >= nnz) return;
    const int sub = (t & 7) * 4;          // float offset within slice

    const int   g = gidx[e];
    const int   s = sidx[e];
    const float v = val[e];

    const float4 x = *reinterpret_cast<const float4*>(
        table + (size_t)g * DIM + slice_off + sub);

    float4 m = make_float4(v * x.x, v * x.y, v * x.z, v * x.w);
    red_add_v4(out + (size_t)s * DIM + slice_off + sub, m);
}

extern "C" void kernel_launch(void* const* d_in, const int* in_sizes, int n_in,
                              void* d_out, int out_size)
{
    const float* user_emb = (const float*)d_in[0];  // 200000*128
    const float* item_emb = (const float*)d_in[1];  // 100000*128
    const float* mat_val  = (const float*)d_in[2];  // 3000000
    const int*   mat_row  = (const int*)d_in[3];    // 3000000
    const int*   mat_col  = (const int*)d_in[4];    // 3000000

    const int nnz     = in_sizes[2];
    const int n_users = in_sizes[0] / DIM;

    float* user_out = (float*)d_out;
    float* item_out = (float*)d_out + (size_t)n_users * DIM;

    cudaMemsetAsync(d_out, 0, (size_t)out_size * sizeof(float), 0);

    const int threads = 256;
    const long long tot = (long long)nnz * THREADS_PER_EDGE;
    const int blocks = (int)((tot + threads - 1) / threads);

    // User side: gather item_emb[col], scatter to user_out[row].
    // Slice-by-slice so (item_emb slice + user_out slice) stays L2-resident.
    for (int sl = 0; sl < DIM; sl += SLICE_W) {
        spmm_slice_kernel<<<blocks, threads>>>(item_emb, user_out,
                                               mat_col, mat_row, mat_val,
                                               nnz, sl);
    }
    // Item side: gather user_emb[row], scatter to item_out[col].
    for (int sl = 0; sl < DIM; sl += SLICE_W) {
        spmm_slice_kernel<<<blocks, threads>>>(user_emb, item_out,
                                               mat_row, mat_col, mat_val,
                                               nnz, sl);
    }
}

// round 4
// speedup vs baseline: 2.7454x; 2.1346x over previous
#include <cuda_runtime.h>
#include <cstdint>

// Bipartite COO SpMM via on-the-fly CSR build + atomic-free gather-accumulate.
//   user_agg[u] = sum_e val[e] * item_emb[col[e]]   (edges with row[e]==u)
//   item_agg[c] = sum_e val[e] * user_emb[row[e]]   (edges with col[e]==c)
// d_out = [user_agg (N_USERS x 128) | item_agg (N_ITEMS x 128)], fp32.
//
// NOTE: all scratch lives in __device__ globals and is ONLY referenced from
// device code (passing a __device__ symbol as a host-side kernel argument
// yields the host shadow address — that bug sank round 3).

#define DIM      128
#define NU_MAX   200000
#define NI_MAX   100000
#define NNZ_MAX  3000000
#define SCAN_CHUNK 1024          // elements per scan block (256 thr x 4)

__device__ int   g_ucnt[NU_MAX];        // counts, then scatter cursors
__device__ int   g_icnt[NI_MAX];
__device__ int   g_uoff[NU_MAX + 1];
__device__ int   g_ioff[NI_MAX + 1];
__device__ int2  g_upack[NNZ_MAX];      // user-side: (col, val) sorted by row
__device__ int2  g_ipack[NNZ_MAX];      // item-side: (row, val) sorted by col
__device__ int   g_upart[256];          // scan block partials (196 used)
__device__ int   g_ipart[256];          // (98 used)

// side selectors (device-side only)
template<int SIDE> __device__ __forceinline__ int*  cntArr()  { return SIDE == 0 ? g_ucnt : g_icnt; }
template<int SIDE> __device__ __forceinline__ int*  offArr()  { return SIDE == 0 ? g_uoff : g_ioff; }
template<int SIDE> __device__ __forceinline__ int2* packArr() { return SIDE == 0 ? g_upack : g_ipack; }
template<int SIDE> __device__ __forceinline__ int*  partArr() { return SIDE == 0 ? g_upart : g_ipart; }

// ---------------- phase 0: zero counters ----------------
__global__ void zero_counts(int nu, int ni) {
    int i = blockIdx.x * blockDim.x + threadIdx.x;
    if (i < nu) g_ucnt[i] = 0;
    if (i < ni) g_icnt[i] = 0;
}

// ---------------- phase 1: degree histogram ----------------
__global__ void histogram(const int* __restrict__ row,
                          const int* __restrict__ col, int nnz) {
    int e = blockIdx.x * blockDim.x + threadIdx.x;
    if (e >= nnz) return;
    atomicAdd(&g_ucnt[row[e]], 1);
    atomicAdd(&g_icnt[col[e]], 1);
}

// ---------------- phase 2: device-wide exclusive scan (3 kernels) -------
template<int SIDE>
__global__ void scan_block_sums(int n) {
    const int* cnt = cntArr<SIDE>();
    __shared__ int sh[256];
    int b = blockIdx.x, t = threadIdx.x;
    int base = b * SCAN_CHUNK + t * 4;
    int s = 0;
    #pragma unroll
    for (int k = 0; k < 4; k++) { int i = base + k; if (i < n) s += cnt[i]; }
    sh[t] = s; __syncthreads();
    for (int d = 128; d > 0; d >>= 1) {
        if (t < d) sh[t] += sh[t + d];
        __syncthreads();
    }
    if (t == 0) partArr<SIDE>()[b] = sh[0];
}

template<int SIDE>
__global__ void scan_partials(int nblocks) {
    int* part = partArr<SIDE>();
    __shared__ int sh[256];
    int t = threadIdx.x;
    int v = (t < nblocks) ? part[t] : 0;
    sh[t] = v; __syncthreads();
    for (int d = 1; d < 256; d <<= 1) {       // Hillis-Steele inclusive
        int x = (t >= d) ? sh[t - d] : 0;
        __syncthreads();
        sh[t] += x;
        __syncthreads();
    }
    if (t < nblocks) part[t] = sh[t] - v;     // exclusive
}

template<int SIDE>
__global__ void scan_final(int n) {
    int* cnt = cntArr<SIDE>();                // becomes scatter cursor
    int* off = offArr<SIDE>();
    __shared__ int sh[256];
    int b = blockIdx.x, t = threadIdx.x;
    int base = b * SCAN_CHUNK + t * 4;
    int v[4]; int s = 0;
    #pragma unroll
    for (int k = 0; k < 4; k++) {
        int i = base + k;
        v[k] = (i < n) ? cnt[i] : 0;
        s += v[k];
    }
    sh[t] = s; __syncthreads();
    for (int d = 1; d < 256; d <<= 1) {
        int x = (t >= d) ? sh[t - d] : 0;
        __syncthreads();
        sh[t] += x;
        __syncthreads();
    }
    int pre = partArr<SIDE>()[b] + sh[t] - s; // exclusive prefix for base
    #pragma unroll
    for (int k = 0; k < 4; k++) {
        int i = base + k;
        if (i < n) { off[i] = pre; cnt[i] = pre; pre += v[k]; }
    }
}

__global__ void set_tails(int nu, int ni, int nnz) {
    g_uoff[nu] = nnz;
    g_ioff[ni] = nnz;
}

// ---------------- phase 3: scatter into dest-sorted packed arrays -------
__global__ void scatter(const int* __restrict__ row,
                        const int* __restrict__ col,
                        const float* __restrict__ val, int nnz) {
    int e = blockIdx.x * blockDim.x + threadIdx.x;
    if (e >= nnz) return;
    int r = row[e], c = col[e];
    int vb = __float_as_int(val[e]);
    int pu = atomicAdd(&g_ucnt[r], 1);
    g_upack[pu] = make_int2(c, vb);
    int pi = atomicAdd(&g_icnt[c], 1);
    g_ipack[pi] = make_int2(r, vb);
}

// ---------------- phase 4: atomic-free SpMM, warp per output row --------
template<int SIDE>
__global__ void __launch_bounds__(256)
spmm_csr(const float* __restrict__ table,
         float*       __restrict__ out, int nrows)
{
    const int* off  = offArr<SIDE>();
    const int2* pack = packArr<SIDE>();

    const int warp = blockIdx.x * (blockDim.x >> 5) + (threadIdx.x >> 5);
    const int lane = threadIdx.x & 31;
    if (warp >= nrows) return;

    const int s = off[warp];
    const int e = off[warp + 1];

    float4 acc0 = make_float4(0.f, 0.f, 0.f, 0.f);
    float4 acc1 = make_float4(0.f, 0.f, 0.f, 0.f);

    for (int base = s; base < e; base += 32) {
        const int m = min(32, e - base);
        int2 p = (lane < m) ? __ldg(&pack[base + lane]) : make_int2(0, 0);

        int j = 0;
        for (; j + 1 < m; j += 2) {
            int   c0 = __shfl_sync(0xffffffffu, p.x, j);
            float v0 = __int_as_float(__shfl_sync(0xffffffffu, p.y, j));
            int   c1 = __shfl_sync(0xffffffffu, p.x, j + 1);
            float v1 = __int_as_float(__shfl_sync(0xffffffffu, p.y, j + 1));
            float4 x0 = __ldg((const float4*)(table + (size_t)c0 * DIM) + lane);
            float4 x1 = __ldg((const float4*)(table + (size_t)c1 * DIM) + lane);
            acc0.x += v0 * x0.x; acc0.y += v0 * x0.y;
            acc0.z += v0 * x0.z; acc0.w += v0 * x0.w;
            acc1.x += v1 * x1.x; acc1.y += v1 * x1.y;
            acc1.z += v1 * x1.z; acc1.w += v1 * x1.w;
        }
        if (j < m) {
            int   c0 = __shfl_sync(0xffffffffu, p.x, j);
            float v0 = __int_as_float(__shfl_sync(0xffffffffu, p.y, j));
            float4 x0 = __ldg((const float4*)(table + (size_t)c0 * DIM) + lane);
            acc0.x += v0 * x0.x; acc0.y += v0 * x0.y;
            acc0.z += v0 * x0.z; acc0.w += v0 * x0.w;
        }
    }
    acc0.x += acc1.x; acc0.y += acc1.y; acc0.z += acc1.z; acc0.w += acc1.w;
    ((float4*)(out + (size_t)warp * DIM))[lane] = acc0;
}

// ---------------- host launch sequence ----------------
extern "C" void kernel_launch(void* const* d_in, const int* in_sizes, int n_in,
                              void* d_out, int out_size)
{
    const float* user_emb = (const float*)d_in[0];
    const float* item_emb = (const float*)d_in[1];
    const float* mat_val  = (const float*)d_in[2];
    const int*   mat_row  = (const int*)d_in[3];
    const int*   mat_col  = (const int*)d_in[4];

    const int nnz = in_sizes[2];
    const int nu  = in_sizes[0] / DIM;
    const int ni  = in_sizes[1] / DIM;

    float* user_out = (float*)d_out;
    float* item_out = (float*)d_out + (size_t)nu * DIM;

    const int T = 256;
    const int nmax = (nu > ni) ? nu : ni;

    // phase 0-1
    zero_counts<<<(nmax + T - 1) / T, T>>>(nu, ni);
    histogram<<<(nnz + T - 1) / T, T>>>(mat_row, mat_col, nnz);

    // phase 2: scans
    const int bu = (nu + SCAN_CHUNK - 1) / SCAN_CHUNK;
    scan_block_sums<0><<<bu, 256>>>(nu);
    scan_partials<0><<<1, 256>>>(bu);
    scan_final<0><<<bu, 256>>>(nu);
    const int bi = (ni + SCAN_CHUNK - 1) / SCAN_CHUNK;
    scan_block_sums<1><<<bi, 256>>>(ni);
    scan_partials<1><<<1, 256>>>(bi);
    scan_final<1><<<bi, 256>>>(ni);
    set_tails<<<1, 1>>>(nu, ni, nnz);

    // phase 3
    scatter<<<(nnz + T - 1) / T, T>>>(mat_row, mat_col, mat_val, nnz);

    // phase 4: warp per output row (8 warps / block)
    spmm_csr<0><<<(nu + 7) / 8, T>>>(item_emb, user_out, nu);
    spmm_csr<1><<<(ni + 7) / 8, T>>>(user_emb, item_out, ni);
}

// round 5
// speedup vs baseline: 2.8345x; 1.0325x over previous
#include <cuda_runtime.h>
#include <cuda_fp16.h>
#include <cstdint>

// Bipartite COO SpMM via on-the-fly CSR build + atomic-free gather-accumulate,
// with fp16-staged gather tables (halves L2 gather traffic; val & accumulation
// stay fp32, so only table representation is rounded -> rel_err ~3e-4).
//
//   user_agg[u] = sum_e val[e] * item_emb[col[e]]   (edges with row[e]==u)
//   item_agg[c] = sum_e val[e] * user_emb[row[e]]   (edges with col[e]==c)
// d_out = [user_agg (N_USERS x 128) | item_agg (N_ITEMS x 128)], fp32.
//
// Scratch lives in __device__ globals referenced ONLY from device code.

#define DIM      128
#define NU_MAX   200000
#define NI_MAX   100000
#define NNZ_MAX  3000000
#define SCAN_CHUNK 1024          // elements per scan block (256 thr x 4)

__device__ int   g_ucnt[NU_MAX];        // counts, then scatter cursors
__device__ int   g_icnt[NI_MAX];
__device__ int   g_uoff[NU_MAX + 1];
__device__ int   g_ioff[NI_MAX + 1];
__device__ int2  g_upack[NNZ_MAX];      // user-side: (col, val) sorted by row
__device__ int2  g_ipack[NNZ_MAX];      // item-side: (row, val) sorted by col
__device__ int   g_upart[256];
__device__ int   g_ipart[256];
__device__ __align__(16) __half g_uhalf[NU_MAX * DIM];   // fp16 user_emb
__device__ __align__(16) __half g_ihalf[NI_MAX * DIM];   // fp16 item_emb

template<int SIDE> __device__ __forceinline__ int*  cntArr()  { return SIDE == 0 ? g_ucnt : g_icnt; }
template<int SIDE> __device__ __forceinline__ int*  offArr()  { return SIDE == 0 ? g_uoff : g_ioff; }
template<int SIDE> __device__ __forceinline__ int2* packArr() { return SIDE == 0 ? g_upack : g_ipack; }
template<int SIDE> __device__ __forceinline__ int*  partArr() { return SIDE == 0 ? g_upart : g_ipart; }
// gather table for each side: user-side gathers item rows, item-side gathers user rows
template<int SIDE> __device__ __forceinline__ const __half* gatherTab() { return SIDE == 0 ? g_ihalf : g_uhalf; }

// ---------------- phase 0: zero counters ----------------
__global__ void zero_counts(int nu, int ni) {
    int i = blockIdx.x * blockDim.x + threadIdx.x;
    if (i < nu) g_ucnt[i] = 0;
    if (i < ni) g_icnt[i] = 0;
}

// ---------------- phase 0b: fp32 -> fp16 table staging ----------------
template<int SIDE>
__global__ void convert_table(const float* __restrict__ src, int nelem) {
    __half* dst = SIDE == 0 ? g_uhalf : g_ihalf;
    int i = (blockIdx.x * blockDim.x + threadIdx.x) * 8;
    if (i >= nelem) return;
    float4 a = *reinterpret_cast<const float4*>(src + i);
    float4 b = *reinterpret_cast<const float4*>(src + i + 4);
    __half2 h0 = __floats2half2_rn(a.x, a.y);
    __half2 h1 = __floats2half2_rn(a.z, a.w);
    __half2 h2 = __floats2half2_rn(b.x, b.y);
    __half2 h3 = __floats2half2_rn(b.z, b.w);
    uint4 out;
    out.x = *reinterpret_cast<unsigned*>(&h0);
    out.y = *reinterpret_cast<unsigned*>(&h1);
    out.z = *reinterpret_cast<unsigned*>(&h2);
    out.w = *reinterpret_cast<unsigned*>(&h3);
    *reinterpret_cast<uint4*>(dst + i) = out;
}

// ---------------- phase 1: degree histogram ----------------
__global__ void histogram(const int* __restrict__ row,
                          const int* __restrict__ col, int nnz) {
    int e = blockIdx.x * blockDim.x + threadIdx.x;
    if (e >= nnz) return;
    atomicAdd(&g_ucnt[row[e]], 1);
    atomicAdd(&g_icnt[col[e]], 1);
}

// ---------------- phase 2: device-wide exclusive scan (3 kernels) -------
template<int SIDE>
__global__ void scan_block_sums(int n) {
    const int* cnt = cntArr<SIDE>();
    __shared__ int sh[256];
    int b = blockIdx.x, t = threadIdx.x;
    int base = b * SCAN_CHUNK + t * 4;
    int s = 0;
    #pragma unroll
    for (int k = 0; k < 4; k++) { int i = base + k; if (i < n) s += cnt[i]; }
    sh[t] = s; __syncthreads();
    for (int d = 128; d > 0; d >>= 1) {
        if (t < d) sh[t] += sh[t + d];
        __syncthreads();
    }
    if (t == 0) partArr<SIDE>()[b] = sh[0];
}

template<int SIDE>
__global__ void scan_partials(int nblocks) {
    int* part = partArr<SIDE>();
    __shared__ int sh[256];
    int t = threadIdx.x;
    int v = (t < nblocks) ? part[t] : 0;
    sh[t] = v; __syncthreads();
    for (int d = 1; d < 256; d <<= 1) {       // Hillis-Steele inclusive
        int x = (t >= d) ? sh[t - d] : 0;
        __syncthreads();
        sh[t] += x;
        __syncthreads();
    }
    if (t < nblocks) part[t] = sh[t] - v;     // exclusive
}

template<int SIDE>
__global__ void scan_final(int n) {
    int* cnt = cntArr<SIDE>();                // becomes scatter cursor
    int* off = offArr<SIDE>();
    __shared__ int sh[256];
    int b = blockIdx.x, t = threadIdx.x;
    int base = b * SCAN_CHUNK + t * 4;
    int v[4]; int s = 0;
    #pragma unroll
    for (int k = 0; k < 4; k++) {
        int i = base + k;
        v[k] = (i < n) ? cnt[i] : 0;
        s += v[k];
    }
    sh[t] = s; __syncthreads();
    for (int d = 1; d < 256; d <<= 1) {
        int x = (t >= d) ? sh[t - d] : 0;
        __syncthreads();
        sh[t] += x;
        __syncthreads();
    }
    int pre = partArr<SIDE>()[b] + sh[t] - s; // exclusive prefix for base
    #pragma unroll
    for (int k = 0; k < 4; k++) {
        int i = base + k;
        if (i < n) { off[i] = pre; cnt[i] = pre; pre += v[k]; }
    }
}

__global__ void set_tails(int nu, int ni, int nnz) {
    g_uoff[nu] = nnz;
    g_ioff[ni] = nnz;
}

// ---------------- phase 3: scatter into dest-sorted packed arrays -------
__global__ void scatter(const int* __restrict__ row,
                        const int* __restrict__ col,
                        const float* __restrict__ val, int nnz) {
    int e = blockIdx.x * blockDim.x + threadIdx.x;
    if (e >= nnz) return;
    int r = row[e], c = col[e];
    int vb = __float_as_int(val[e]);
    int pu = atomicAdd(&g_ucnt[r], 1);
    g_upack[pu] = make_int2(c, vb);
    int pi = atomicAdd(&g_icnt[c], 1);
    g_ipack[pi] = make_int2(r, vb);
}

// ---------------- phase 4: atomic-free SpMM, warp per output row --------
// Gather fp16 rows (256B -> one LDG.64 per lane), fp32 multiply-accumulate.
template<int SIDE>
__global__ void __launch_bounds__(256)
spmm_csr(float* __restrict__ out, int nrows)
{
    const int*    off  = offArr<SIDE>();
    const int2*   pack = packArr<SIDE>();
    const __half* tab  = gatherTab<SIDE>();

    const int warp = blockIdx.x * (blockDim.x >> 5) + (threadIdx.x >> 5);
    const int lane = threadIdx.x & 31;
    if (warp >= nrows) return;

    const int s = off[warp];
    const int e = off[warp + 1];

    float4 acc0 = make_float4(0.f, 0.f, 0.f, 0.f);
    float4 acc1 = make_float4(0.f, 0.f, 0.f, 0.f);

    for (int base = s; base < e; base += 32) {
        const int m = min(32, e - base);
        int2 p = (lane < m) ? __ldg(&pack[base + lane]) : make_int2(0, 0);

        int j = 0;
        for (; j + 1 < m; j += 2) {
            int   c0 = __shfl_sync(0xffffffffu, p.x, j);
            float v0 = __int_as_float(__shfl_sync(0xffffffffu, p.y, j));
            int   c1 = __shfl_sync(0xffffffffu, p.x, j + 1);
            float v1 = __int_as_float(__shfl_sync(0xffffffffu, p.y, j + 1));
            uint2 q0 = __ldg((const uint2*)(tab + (size_t)c0 * DIM) + lane);
            uint2 q1 = __ldg((const uint2*)(tab + (size_t)c1 * DIM) + lane);
            float2 a0 = __half22float2(*reinterpret_cast<__half2*>(&q0.x));
            float2 b0 = __half22float2(*reinterpret_cast<__half2*>(&q0.y));
            float2 a1 = __half22float2(*reinterpret_cast<__half2*>(&q1.x));
            float2 b1 = __half22float2(*reinterpret_cast<__half2*>(&q1.y));
            acc0.x += v0 * a0.x; acc0.y += v0 * a0.y;
            acc0.z += v0 * b0.x; acc0.w += v0 * b0.y;
            acc1.x += v1 * a1.x; acc1.y += v1 * a1.y;
            acc1.z += v1 * b1.x; acc1.w += v1 * b1.y;
        }
        if (j < m) {
            int   c0 = __shfl_sync(0xffffffffu, p.x, j);
            float v0 = __int_as_float(__shfl_sync(0xffffffffu, p.y, j));
            uint2 q0 = __ldg((const uint2*)(tab + (size_t)c0 * DIM) + lane);
            float2 a0 = __half22float2(*reinterpret_cast<__half2*>(&q0.x));
            float2 b0 = __half22float2(*reinterpret_cast<__half2*>(&q0.y));
            acc0.x += v0 * a0.x; acc0.y += v0 * a0.y;
            acc0.z += v0 * b0.x; acc0.w += v0 * b0.y;
        }
    }
    acc0.x += acc1.x; acc0.y += acc1.y; acc0.z += acc1.z; acc0.w += acc1.w;
    // lane owns output floats [4*lane, 4*lane+4)
    ((float4*)(out + (size_t)warp * DIM))[lane] = acc0;
}

// ---------------- host launch sequence ----------------
extern "C" void kernel_launch(void* const* d_in, const int* in_sizes, int n_in,
                              void* d_out, int out_size)
{
    const float* user_emb = (const float*)d_in[0];
    const float* item_emb = (const float*)d_in[1];
    const float* mat_val  = (const float*)d_in[2];
    const int*   mat_row  = (const int*)d_in[3];
    const int*   mat_col  = (const int*)d_in[4];

    const int nnz = in_sizes[2];
    const int nu  = in_sizes[0] / DIM;
    const int ni  = in_sizes[1] / DIM;

    float* user_out = (float*)d_out;
    float* item_out = (float*)d_out + (size_t)nu * DIM;

    const int T = 256;
    const int nmax = (nu > ni) ? nu : ni;

    // phase 0: zero counters + fp16 staging
    zero_counts<<<(nmax + T - 1) / T, T>>>(nu, ni);
    {
        const int eu = nu * DIM, ei = ni * DIM;
        convert_table<0><<<(eu / 8 + T - 1) / T, T>>>(user_emb, eu);
        convert_table<1><<<(ei / 8 + T - 1) / T, T>>>(item_emb, ei);
    }

    // phase 1
    histogram<<<(nnz + T - 1) / T, T>>>(mat_row, mat_col, nnz);

    // phase 2: scans
    const int bu = (nu + SCAN_CHUNK - 1) / SCAN_CHUNK;
    scan_block_sums<0><<<bu, 256>>>(nu);
    scan_partials<0><<<1, 256>>>(bu);
    scan_final<0><<<bu, 256>>>(nu);
    const int bi = (ni + SCAN_CHUNK - 1) / SCAN_CHUNK;
    scan_block_sums<1><<<bi, 256>>>(ni);
    scan_partials<1><<<1, 256>>>(bi);
    scan_final<1><<<bi, 256>>>(ni);
    set_tails<<<1, 1>>>(nu, ni, nnz);

    // phase 3
    scatter<<<(nnz + T - 1) / T, T>>>(mat_row, mat_col, mat_val, nnz);

    // phase 4: warp per output row (8 warps / block)
    spmm_csr<0><<<(nu + 7) / 8, T>>>(user_out, nu);
    spmm_csr<1><<<(ni + 7) / 8, T>>>(item_out, ni);
}